// round 4
// baseline (speedup 1.0000x reference)
#include <cuda_runtime.h>
#include <math_constants.h>

#define N_NODES 100000
#define N_EDGES 1600000
#define N_GRAPHS 256
#define HDIM 32
#define UPD 128
#define SCAN_B 1024
#define SCAN_NB ((N_NODES + SCAN_B - 1) / SCAN_B)   // 98

// ---------------- scratch (device globals; no allocation) ----------------
__device__ int   d_deg[N_NODES];               // in-degree (also layer3 mean cnt)
__device__ int   d_rowptr[N_NODES];            // CSR row starts (by dst)
__device__ int   d_cursor[N_NODES];            // fill cursors
__device__ int   d_bsum[128];                  // scan block sums
__device__ int   d_col[N_EDGES];               // CSR column (src) indices
__device__ float d_agg32[N_NODES * HDIM];      // layer2 aggregate
__device__ float d_agg32b[N_NODES * HDIM];     // layer3 aggregate
__device__ float d_h1[N_NODES * HDIM];
__device__ float d_h2[N_NODES * HDIM];
__device__ float d_sum[N_GRAPHS * UPD];        // add pool
__device__ float d_maxp[N_GRAPHS * UPD];       // max pool
__device__ float d_gcnt[N_GRAPHS];             // nodes per graph

__device__ __forceinline__ float lrelu(float v) { return v > 0.f ? v : 0.01f * v; }

__device__ __forceinline__ void atomicMaxF(float* addr, float v) {
    if (v >= 0.f) atomicMax((int*)addr, __float_as_int(v));
    else          atomicMin((unsigned int*)addr, __float_as_uint(v));
}

// ---------------- init (tiny now: no big aggregate zeroing) ----------------
__global__ void k_init() {
    int i = blockIdx.x * blockDim.x + threadIdx.x;
    if (i < N_NODES) d_deg[i] = 0;
    if (i < N_GRAPHS * UPD) { d_sum[i] = 0.f; d_maxp[i] = -CUDART_INF_F; }
    if (i < N_GRAPHS) d_gcnt[i] = 0.f;
}

// ---------------- graph node counts (batch sorted, hist per block) -------
__global__ void k_gcnt(const int* __restrict__ batch) {
    __shared__ int hist[N_GRAPHS];
    int t = threadIdx.x;
    for (int i = t; i < N_GRAPHS; i += blockDim.x) hist[i] = 0;
    __syncthreads();
    for (int i = blockIdx.x * blockDim.x + t; i < N_NODES; i += gridDim.x * blockDim.x)
        atomicAdd(&hist[batch[i]], 1);
    __syncthreads();
    for (int i = t; i < N_GRAPHS; i += blockDim.x)
        if (hist[i]) atomicAdd(&d_gcnt[i], (float)hist[i]);
}

// ---------------- CSR build: histogram -> scan -> fill ----------------
__global__ void k_hist(const int* __restrict__ ei) {
    int e = blockIdx.x * blockDim.x + threadIdx.x;
    if (e >= N_EDGES) return;
    atomicAdd(&d_deg[__ldg(&ei[N_EDGES + e])], 1);
}

__global__ void k_scan_block() {
    __shared__ int sm[SCAN_B];
    int b = blockIdx.x, t = threadIdx.x;
    int i = b * SCAN_B + t;
    int v = (i < N_NODES) ? d_deg[i] : 0;
    sm[t] = v;
    __syncthreads();
    for (int off = 1; off < SCAN_B; off <<= 1) {
        int add = (t >= off) ? sm[t - off] : 0;
        __syncthreads();
        sm[t] += add;
        __syncthreads();
    }
    if (i < N_NODES) d_rowptr[i] = sm[t] - v;    // exclusive
    if (t == SCAN_B - 1) d_bsum[b] = sm[t];      // block total
}

__global__ void k_scan_bsum() {   // 1 block, 128 threads
    __shared__ int sm[128];
    int t = threadIdx.x;
    int v = (t < SCAN_NB) ? d_bsum[t] : 0;
    sm[t] = v;
    __syncthreads();
    for (int off = 1; off < 128; off <<= 1) {
        int add = (t >= off) ? sm[t - off] : 0;
        __syncthreads();
        sm[t] += add;
        __syncthreads();
    }
    d_bsum[t] = sm[t] - v;                        // exclusive block offsets
}

__global__ void k_scan_add() {
    int i = blockIdx.x * blockDim.x + threadIdx.x;
    if (i >= N_NODES) return;
    int r = d_rowptr[i] + d_bsum[i / SCAN_B];
    d_rowptr[i] = r;
    d_cursor[i] = r;
}

__global__ void k_fill(const int* __restrict__ ei) {
    int e = blockIdx.x * blockDim.x + threadIdx.x;
    if (e >= N_EDGES) return;
    int s = __ldg(&ei[e]);
    int d = __ldg(&ei[N_EDGES + e]);
    int pos = atomicAdd(&d_cursor[d], 1);
    d_col[pos] = s;
}

// ---------------- layer 1: fused scalar gather + node transform ----------
__global__ void k_g1_node1(const float* __restrict__ x,
                           const float* __restrict__ W1l, const float* __restrict__ b1,
                           const float* __restrict__ W1r) {
    int w = (blockIdx.x * blockDim.x + threadIdx.x) >> 5;
    int lane = threadIdx.x & 31;
    if (w >= N_NODES) return;
    int start = d_rowptr[w], deg = d_deg[w];
    float p = 0.f;
    for (int j = lane; j < deg; j += 32)
        p += __ldg(&x[__ldg(&d_col[start + j])]);
#pragma unroll
    for (int o = 16; o > 0; o >>= 1) p += __shfl_down_sync(0xffffffffu, p, o);
    p = __shfl_sync(0xffffffffu, p, 0);
    d_h1[w * HDIM + lane] =
        lrelu(p * __ldg(&W1l[lane]) + __ldg(&b1[lane]) + __ldg(&x[w]) * __ldg(&W1r[lane]));
}

// ---------------- 32-wide gather: warp per node, plain stores ----------
__global__ void k_gather32(int phase) {
    int w = (blockIdx.x * blockDim.x + threadIdx.x) >> 5;
    int lane = threadIdx.x & 31;
    if (w >= N_NODES) return;
    const float* __restrict__ src = phase ? d_h2 : d_h1;
    float* __restrict__ dst = phase ? d_agg32b : d_agg32;
    int start = d_rowptr[w], deg = d_deg[w];
    float acc = 0.f;
    for (int j0 = 0; j0 < deg; j0 += 32) {
        int idx = j0 + lane;
        int mys = (idx < deg) ? __ldg(&d_col[start + idx]) : 0;
        int m = min(32, deg - j0);
#pragma unroll 4
        for (int k = 0; k < m; k++) {
            int s = __shfl_sync(0xffffffffu, mys, k);
            acc += __ldg(&src[s * HDIM + lane]);
        }
    }
    dst[w * HDIM + lane] = acc;
}

// ---------------- layer 2 node transform ----------------
__global__ void k_node2(const float* __restrict__ W2l, const float* __restrict__ b2,
                        const float* __restrict__ W2r) {
    __shared__ float sWl[HDIM * HDIM], sWr[HDIM * HDIM];
    __shared__ float sA[8 * HDIM], sH[8 * HDIM];
    int t = threadIdx.x;
    for (int i = t; i < HDIM * HDIM; i += 256) { sWl[i] = W2l[i]; sWr[i] = W2r[i]; }
    int base = blockIdx.x * 8;
    int node = base + (t >> 5);
    int j = t & 31;
    if (node < N_NODES) {
        sA[t] = d_agg32[node * HDIM + j];
        sH[t] = d_h1[node * HDIM + j];
    }
    __syncthreads();
    if (node >= N_NODES) return;
    int ns = t >> 5;
    float acc = __ldg(&b2[j]);
#pragma unroll
    for (int k = 0; k < HDIM; k++)
        acc += sA[ns * HDIM + k] * sWl[k * HDIM + j] + sH[ns * HDIM + k] * sWr[k * HDIM + j];
    d_h2[node * HDIM + j] = lrelu(acc);
}

// ---------------- layer 3 (mean) + upsample + pooling (fused) ----------
__global__ void __launch_bounds__(128) k_node3_up_pool(
    const float* __restrict__ W3l, const float* __restrict__ b3,
    const float* __restrict__ W3r, const float* __restrict__ Wu,
    const float* __restrict__ bu, const int* __restrict__ batch) {
    __shared__ float sWl[HDIM * HDIM], sWr[HDIM * HDIM], sWu[HDIM * UPD];
    __shared__ float sA[32 * HDIM], sB[32 * HDIM], sH3[32 * HDIM];
    __shared__ float sb3[HDIM], sbu[UPD];
    __shared__ int sG[32];
    int t = threadIdx.x;
    for (int i = t; i < HDIM * HDIM; i += 128) { sWl[i] = W3l[i]; sWr[i] = W3r[i]; }
    for (int i = t; i < HDIM * UPD; i += 128) sWu[i] = Wu[i];
    if (t < HDIM) sb3[t] = b3[t];
    sbu[t] = bu[t];

    int base = blockIdx.x * 32;
    for (int i = t; i < 32 * HDIM; i += 128) {
        int node = base + (i >> 5);
        if (node < N_NODES) {
            float c = (float)d_deg[node];
            sA[i] = d_agg32b[node * HDIM + (i & 31)] / fmaxf(c, 1.f);
            sB[i] = d_h2[node * HDIM + (i & 31)];
        } else { sA[i] = 0.f; sB[i] = 0.f; }
    }
    if (t < 32) {
        int node = base + t;
        sG[t] = node < N_NODES ? batch[node] : -1;
    }
    __syncthreads();

    // h3 = lrelu(agg/cnt @ W3l + b3 + h2 @ W3r)
    for (int i = t; i < 32 * HDIM; i += 128) {
        int n = i >> 5, j = i & 31;
        float acc = sb3[j];
#pragma unroll
        for (int k = 0; k < HDIM; k++)
            acc += sA[n * HDIM + k] * sWl[k * HDIM + j] + sB[n * HDIM + k] * sWr[k * HDIM + j];
        sH3[i] = lrelu(acc);
    }
    __syncthreads();

    // h = lrelu(h3 @ Wu + bu); accumulate pools in regs, flush on graph change
    int u = t;
    float regS = 0.f, regM = -CUDART_INF_F;
    int gcur = -1;
    for (int n = 0; n < 32; n++) {
        int g = sG[n];
        if (g < 0) break;
        float acc = sbu[u];
#pragma unroll
        for (int k = 0; k < HDIM; k++)
            acc += sH3[n * HDIM + k] * sWu[k * UPD + u];
        acc = lrelu(acc);
        if (g != gcur) {
            if (gcur >= 0) {
                atomicAdd(&d_sum[gcur * UPD + u], regS);
                atomicMaxF(&d_maxp[gcur * UPD + u], regM);
            }
            gcur = g; regS = 0.f; regM = -CUDART_INF_F;
        }
        regS += acc;
        regM = fmaxf(regM, acc);
    }
    if (gcur >= 0) {
        atomicAdd(&d_sum[gcur * UPD + u], regS);
        atomicMaxF(&d_maxp[gcur * UPD + u], regM);
    }
}

// ---------------- final MLP per graph ----------------
__global__ void k_final(const float* __restrict__ Wf1, const float* __restrict__ bf1,
                        const float* __restrict__ Wf2, const float* __restrict__ bf2,
                        float* __restrict__ out) {
    __shared__ float sZ[3 * UPD], sT[UPD];
    int g = blockIdx.x, t = threadIdx.x;  // 128 threads
    float c = d_gcnt[g];
    float s = d_sum[g * UPD + t];
    sZ[t] = s / fmaxf(c, 1.f);          // mean pool
    sZ[UPD + t] = d_maxp[g * UPD + t];  // max pool
    sZ[2 * UPD + t] = s;                // add pool
    __syncthreads();
    float acc = __ldg(&bf1[t]);
#pragma unroll 8
    for (int k = 0; k < 3 * UPD; k++)
        acc += sZ[k] * __ldg(&Wf1[k * UPD + t]);
    sT[t] = lrelu(acc);
    __syncthreads();
    if (t < 51) {
        float o = __ldg(&bf2[t]);
#pragma unroll 8
        for (int k = 0; k < UPD; k++)
            o += sT[k] * __ldg(&Wf2[k * 51 + t]);
        out[g * 51 + t] = o;
    }
}

// ---------------- launch ----------------
extern "C" void kernel_launch(void* const* d_in, const int* in_sizes, int n_in,
                              void* d_out, int out_size) {
    const float* x     = (const float*)d_in[0];
    const int* ei      = (const int*)d_in[1];    // int32 (JAX x64 disabled)
    const int* batch   = (const int*)d_in[2];    // int32
    const float* W1l = (const float*)d_in[3];
    const float* b1  = (const float*)d_in[4];
    const float* W1r = (const float*)d_in[5];
    const float* W2l = (const float*)d_in[6];
    const float* b2  = (const float*)d_in[7];
    const float* W2r = (const float*)d_in[8];
    const float* W3l = (const float*)d_in[9];
    const float* b3  = (const float*)d_in[10];
    const float* W3r = (const float*)d_in[11];
    const float* Wu  = (const float*)d_in[12];
    const float* bu  = (const float*)d_in[13];
    const float* Wf1 = (const float*)d_in[14];
    const float* bf1 = (const float*)d_in[15];
    const float* Wf2 = (const float*)d_in[16];
    const float* bf2 = (const float*)d_in[17];
    float* out = (float*)d_out;

    k_init<<<(N_NODES + 255) / 256, 256>>>();
    k_gcnt<<<64, 256>>>(batch);
    k_hist<<<(N_EDGES + 255) / 256, 256>>>(ei);
    k_scan_block<<<SCAN_NB, SCAN_B>>>();
    k_scan_bsum<<<1, 128>>>();
    k_scan_add<<<(N_NODES + 255) / 256, 256>>>();
    k_fill<<<(N_EDGES + 255) / 256, 256>>>(ei);

    int gblocks = (int)(((long long)N_NODES * 32 + 255) / 256);
    k_g1_node1<<<gblocks, 256>>>(x, W1l, b1, W1r);
    k_gather32<<<gblocks, 256>>>(0);
    k_node2<<<(N_NODES + 7) / 8, 256>>>(W2l, b2, W2r);
    k_gather32<<<gblocks, 256>>>(1);
    k_node3_up_pool<<<(N_NODES + 31) / 32, 128>>>(W3l, b3, W3r, Wu, bu, batch);
    k_final<<<N_GRAPHS, 128>>>(Wf1, bf1, Wf2, bf2, out);
}

// round 5
// speedup vs baseline: 1.1931x; 1.1931x over previous
#include <cuda_runtime.h>
#include <math_constants.h>

#define N_NODES 100000
#define N_EDGES 1600000
#define N_GRAPHS 256
#define HDIM 32
#define UPD 128
#define SCAN_B 1024
#define SCAN_NB ((N_NODES + SCAN_B - 1) / SCAN_B)   // 98

// ---------------- scratch (device globals; no allocation) ----------------
__device__ int   d_deg[N_NODES];               // in-degree (also layer3 mean cnt)
__device__ int   d_rowptr[N_NODES];            // CSR row starts (by dst)
__device__ int   d_cursor[N_NODES];            // fill cursors
__device__ int   d_bsum[128];                  // scan block sums
__device__ int   d_col[N_EDGES];               // CSR column (src) indices
__device__ float d_agg32[N_NODES * HDIM];      // layer2 aggregate
__device__ float d_agg32b[N_NODES * HDIM];     // layer3 aggregate
__device__ float d_h1[N_NODES * HDIM];
__device__ float d_h2[N_NODES * HDIM];
__device__ float d_sum[N_GRAPHS * UPD];        // add pool
__device__ float d_maxp[N_GRAPHS * UPD];       // max pool
__device__ float d_gcnt[N_GRAPHS];             // nodes per graph

__device__ __forceinline__ float lrelu(float v) { return v > 0.f ? v : 0.01f * v; }

__device__ __forceinline__ void atomicMaxF(float* addr, float v) {
    if (v >= 0.f) atomicMax((int*)addr, __float_as_int(v));
    else          atomicMin((unsigned int*)addr, __float_as_uint(v));
}

// ---------------- init ----------------
__global__ void k_init() {
    int i = blockIdx.x * blockDim.x + threadIdx.x;
    if (i < N_NODES) d_deg[i] = 0;
    if (i < N_GRAPHS * UPD) { d_sum[i] = 0.f; d_maxp[i] = -CUDART_INF_F; }
    if (i < N_GRAPHS) d_gcnt[i] = 0.f;
}

// ---------------- graph node counts (batch sorted, hist per block) -------
__global__ void k_gcnt(const int* __restrict__ batch) {
    __shared__ int hist[N_GRAPHS];
    int t = threadIdx.x;
    for (int i = t; i < N_GRAPHS; i += blockDim.x) hist[i] = 0;
    __syncthreads();
    for (int i = blockIdx.x * blockDim.x + t; i < N_NODES; i += gridDim.x * blockDim.x)
        atomicAdd(&hist[batch[i]], 1);
    __syncthreads();
    for (int i = t; i < N_GRAPHS; i += blockDim.x)
        if (hist[i]) atomicAdd(&d_gcnt[i], (float)hist[i]);
}

// ---------------- CSR build: histogram -> scan -> fill ----------------
__global__ void k_hist(const int* __restrict__ ei) {
    int e = blockIdx.x * blockDim.x + threadIdx.x;
    if (e >= N_EDGES) return;
    atomicAdd(&d_deg[__ldg(&ei[N_EDGES + e])], 1);
}

__global__ void k_scan_block() {
    __shared__ int sm[SCAN_B];
    int b = blockIdx.x, t = threadIdx.x;
    int i = b * SCAN_B + t;
    int v = (i < N_NODES) ? d_deg[i] : 0;
    sm[t] = v;
    __syncthreads();
    for (int off = 1; off < SCAN_B; off <<= 1) {
        int add = (t >= off) ? sm[t - off] : 0;
        __syncthreads();
        sm[t] += add;
        __syncthreads();
    }
    if (i < N_NODES) d_rowptr[i] = sm[t] - v;    // exclusive
    if (t == SCAN_B - 1) d_bsum[b] = sm[t];      // block total
}

__global__ void k_scan_bsum() {   // 1 block, 128 threads
    __shared__ int sm[128];
    int t = threadIdx.x;
    int v = (t < SCAN_NB) ? d_bsum[t] : 0;
    sm[t] = v;
    __syncthreads();
    for (int off = 1; off < 128; off <<= 1) {
        int add = (t >= off) ? sm[t - off] : 0;
        __syncthreads();
        sm[t] += add;
        __syncthreads();
    }
    d_bsum[t] = sm[t] - v;                        // exclusive block offsets
}

__global__ void k_scan_add() {
    int i = blockIdx.x * blockDim.x + threadIdx.x;
    if (i >= N_NODES) return;
    int r = d_rowptr[i] + d_bsum[i / SCAN_B];
    d_rowptr[i] = r;
    d_cursor[i] = r;
}

__global__ void k_fill(const int* __restrict__ ei) {
    int e = blockIdx.x * blockDim.x + threadIdx.x;
    if (e >= N_EDGES) return;
    int s = __ldg(&ei[e]);
    int d = __ldg(&ei[N_EDGES + e]);
    int pos = atomicAdd(&d_cursor[d], 1);
    d_col[pos] = s;
}

// ---------------- layer 1: fused scalar gather + node transform ----------
__global__ void k_g1_node1(const float* __restrict__ x,
                           const float* __restrict__ W1l, const float* __restrict__ b1,
                           const float* __restrict__ W1r) {
    int w = (blockIdx.x * blockDim.x + threadIdx.x) >> 5;
    int lane = threadIdx.x & 31;
    if (w >= N_NODES) return;
    int start = d_rowptr[w], deg = d_deg[w];
    float p = 0.f;
    for (int j = lane; j < deg; j += 32)
        p += __ldg(&x[__ldg(&d_col[start + j])]);
#pragma unroll
    for (int o = 16; o > 0; o >>= 1) p += __shfl_down_sync(0xffffffffu, p, o);
    p = __shfl_sync(0xffffffffu, p, 0);
    d_h1[w * HDIM + lane] =
        lrelu(p * __ldg(&W1l[lane]) + __ldg(&b1[lane]) + __ldg(&x[w]) * __ldg(&W1r[lane]));
}

// ---------------- 32-wide gather: warp/node, 4 groups x 8 lanes (float4),
//                  2 edges per group per iter -> 8 loads in flight ----------
__global__ void __launch_bounds__(256) k_gather32(int phase) {
    int w = (blockIdx.x * blockDim.x + threadIdx.x) >> 5;
    int lane = threadIdx.x & 31;
    if (w >= N_NODES) return;
    int g = lane >> 3;          // group 0..3 (edge slot)
    int sub = lane & 7;         // feature quad 0..7
    const float* __restrict__ src = phase ? d_h2 : d_h1;
    float* __restrict__ dst = phase ? d_agg32b : d_agg32;
    const int* __restrict__ col = d_col;
    int start = d_rowptr[w], deg = d_deg[w];

    float4 a0 = make_float4(0.f, 0.f, 0.f, 0.f);
    float4 a1 = make_float4(0.f, 0.f, 0.f, 0.f);
    int j = g;
    for (; j + 4 < deg; j += 8) {
        int s0 = __ldg(&col[start + j]);
        int s1 = __ldg(&col[start + j + 4]);
        float4 v0 = *(const float4*)&src[s0 * HDIM + sub * 4];
        float4 v1 = *(const float4*)&src[s1 * HDIM + sub * 4];
        a0.x += v0.x; a0.y += v0.y; a0.z += v0.z; a0.w += v0.w;
        a1.x += v1.x; a1.y += v1.y; a1.z += v1.z; a1.w += v1.w;
    }
    if (j < deg) {
        int s0 = __ldg(&col[start + j]);
        float4 v0 = *(const float4*)&src[s0 * HDIM + sub * 4];
        a0.x += v0.x; a0.y += v0.y; a0.z += v0.z; a0.w += v0.w;
    }
    a0.x += a1.x; a0.y += a1.y; a0.z += a1.z; a0.w += a1.w;
    // reduce across the 4 groups (xor 8, 16)
#pragma unroll
    for (int o = 8; o <= 16; o <<= 1) {
        a0.x += __shfl_xor_sync(0xffffffffu, a0.x, o);
        a0.y += __shfl_xor_sync(0xffffffffu, a0.y, o);
        a0.z += __shfl_xor_sync(0xffffffffu, a0.z, o);
        a0.w += __shfl_xor_sync(0xffffffffu, a0.w, o);
    }
    if (lane < 8)
        *(float4*)&dst[w * HDIM + sub * 4] = a0;
}

// ---------------- layer 2 node transform ----------------
__global__ void k_node2(const float* __restrict__ W2l, const float* __restrict__ b2,
                        const float* __restrict__ W2r) {
    __shared__ float sWl[HDIM * HDIM], sWr[HDIM * HDIM];
    __shared__ float sA[8 * HDIM], sH[8 * HDIM];
    int t = threadIdx.x;
    for (int i = t; i < HDIM * HDIM; i += 256) { sWl[i] = W2l[i]; sWr[i] = W2r[i]; }
    int base = blockIdx.x * 8;
    int node = base + (t >> 5);
    int j = t & 31;
    if (node < N_NODES) {
        sA[t] = d_agg32[node * HDIM + j];
        sH[t] = d_h1[node * HDIM + j];
    }
    __syncthreads();
    if (node >= N_NODES) return;
    int ns = t >> 5;
    float acc = __ldg(&b2[j]);
#pragma unroll
    for (int k = 0; k < HDIM; k++)
        acc += sA[ns * HDIM + k] * sWl[k * HDIM + j] + sH[ns * HDIM + k] * sWr[k * HDIM + j];
    d_h2[node * HDIM + j] = lrelu(acc);
}

// ---------------- layer 3 (mean) + upsample + pooling (fused) ----------
__global__ void __launch_bounds__(128) k_node3_up_pool(
    const float* __restrict__ W3l, const float* __restrict__ b3,
    const float* __restrict__ W3r, const float* __restrict__ Wu,
    const float* __restrict__ bu, const int* __restrict__ batch) {
    __shared__ float sWl[HDIM * HDIM], sWr[HDIM * HDIM], sWu[HDIM * UPD];
    __shared__ float sA[32 * HDIM], sB[32 * HDIM], sH3[32 * HDIM];
    __shared__ float sb3[HDIM], sbu[UPD];
    __shared__ int sG[32];
    int t = threadIdx.x;
    for (int i = t; i < HDIM * HDIM; i += 128) { sWl[i] = W3l[i]; sWr[i] = W3r[i]; }
    for (int i = t; i < HDIM * UPD; i += 128) sWu[i] = Wu[i];
    if (t < HDIM) sb3[t] = b3[t];
    sbu[t] = bu[t];

    int base = blockIdx.x * 32;
    for (int i = t; i < 32 * HDIM; i += 128) {
        int node = base + (i >> 5);
        if (node < N_NODES) {
            float c = (float)d_deg[node];
            sA[i] = d_agg32b[node * HDIM + (i & 31)] / fmaxf(c, 1.f);
            sB[i] = d_h2[node * HDIM + (i & 31)];
        } else { sA[i] = 0.f; sB[i] = 0.f; }
    }
    if (t < 32) {
        int node = base + t;
        sG[t] = node < N_NODES ? batch[node] : -1;
    }
    __syncthreads();

    // h3 = lrelu(agg/cnt @ W3l + b3 + h2 @ W3r)
    for (int i = t; i < 32 * HDIM; i += 128) {
        int n = i >> 5, j = i & 31;
        float acc = sb3[j];
#pragma unroll
        for (int k = 0; k < HDIM; k++)
            acc += sA[n * HDIM + k] * sWl[k * HDIM + j] + sB[n * HDIM + k] * sWr[k * HDIM + j];
        sH3[i] = lrelu(acc);
    }
    __syncthreads();

    // h = lrelu(h3 @ Wu + bu); accumulate pools in regs, flush on graph change
    int u = t;
    // cache this thread's Wu column in registers (reused across all 32 nodes)
    float wcol[HDIM];
#pragma unroll
    for (int k = 0; k < HDIM; k++) wcol[k] = sWu[k * UPD + u];
    float regS = 0.f, regM = -CUDART_INF_F;
    int gcur = -1;
    for (int n = 0; n < 32; n++) {
        int g = sG[n];
        if (g < 0) break;
        float acc = sbu[u];
#pragma unroll
        for (int k = 0; k < HDIM; k++)
            acc += sH3[n * HDIM + k] * wcol[k];
        acc = lrelu(acc);
        if (g != gcur) {
            if (gcur >= 0) {
                atomicAdd(&d_sum[gcur * UPD + u], regS);
                atomicMaxF(&d_maxp[gcur * UPD + u], regM);
            }
            gcur = g; regS = 0.f; regM = -CUDART_INF_F;
        }
        regS += acc;
        regM = fmaxf(regM, acc);
    }
    if (gcur >= 0) {
        atomicAdd(&d_sum[gcur * UPD + u], regS);
        atomicMaxF(&d_maxp[gcur * UPD + u], regM);
    }
}

// ---------------- final MLP per graph ----------------
__global__ void k_final(const float* __restrict__ Wf1, const float* __restrict__ bf1,
                        const float* __restrict__ Wf2, const float* __restrict__ bf2,
                        float* __restrict__ out) {
    __shared__ float sZ[3 * UPD], sT[UPD];
    int g = blockIdx.x, t = threadIdx.x;  // 128 threads
    float c = d_gcnt[g];
    float s = d_sum[g * UPD + t];
    sZ[t] = s / fmaxf(c, 1.f);          // mean pool
    sZ[UPD + t] = d_maxp[g * UPD + t];  // max pool
    sZ[2 * UPD + t] = s;                // add pool
    __syncthreads();
    float acc = __ldg(&bf1[t]);
#pragma unroll 8
    for (int k = 0; k < 3 * UPD; k++)
        acc += sZ[k] * __ldg(&Wf1[k * UPD + t]);
    sT[t] = lrelu(acc);
    __syncthreads();
    if (t < 51) {
        float o = __ldg(&bf2[t]);
#pragma unroll 8
        for (int k = 0; k < UPD; k++)
            o += sT[k] * __ldg(&Wf2[k * 51 + t]);
        out[g * 51 + t] = o;
    }
}

// ---------------- launch ----------------
extern "C" void kernel_launch(void* const* d_in, const int* in_sizes, int n_in,
                              void* d_out, int out_size) {
    const float* x     = (const float*)d_in[0];
    const int* ei      = (const int*)d_in[1];    // int32 (JAX x64 disabled)
    const int* batch   = (const int*)d_in[2];    // int32
    const float* W1l = (const float*)d_in[3];
    const float* b1  = (const float*)d_in[4];
    const float* W1r = (const float*)d_in[5];
    const float* W2l = (const float*)d_in[6];
    const float* b2  = (const float*)d_in[7];
    const float* W2r = (const float*)d_in[8];
    const float* W3l = (const float*)d_in[9];
    const float* b3  = (const float*)d_in[10];
    const float* W3r = (const float*)d_in[11];
    const float* Wu  = (const float*)d_in[12];
    const float* bu  = (const float*)d_in[13];
    const float* Wf1 = (const float*)d_in[14];
    const float* bf1 = (const float*)d_in[15];
    const float* Wf2 = (const float*)d_in[16];
    const float* bf2 = (const float*)d_in[17];
    float* out = (float*)d_out;

    k_init<<<(N_NODES + 255) / 256, 256>>>();
    k_gcnt<<<64, 256>>>(batch);
    k_hist<<<(N_EDGES + 255) / 256, 256>>>(ei);
    k_scan_block<<<SCAN_NB, SCAN_B>>>();
    k_scan_bsum<<<1, 128>>>();
    k_scan_add<<<(N_NODES + 255) / 256, 256>>>();
    k_fill<<<(N_EDGES + 255) / 256, 256>>>(ei);

    int gblocks = (int)(((long long)N_NODES * 32 + 255) / 256);
    k_g1_node1<<<gblocks, 256>>>(x, W1l, b1, W1r);
    k_gather32<<<gblocks, 256>>>(0);
    k_node2<<<(N_NODES + 7) / 8, 256>>>(W2l, b2, W2r);
    k_gather32<<<gblocks, 256>>>(1);
    k_node3_up_pool<<<(N_NODES + 31) / 32, 128>>>(W3l, b3, W3r, Wu, bu, batch);
    k_final<<<N_GRAPHS, 128>>>(Wf1, bf1, Wf2, bf2, out);
}